// round 6
// baseline (speedup 1.0000x reference)
#include <cuda_runtime.h>

// Problem constants (fixed by the reference)
#define BB   4
#define CC   32
#define HH   64
#define WW   64
#define KK   64
#define HWV  (HH*WW)      // 4096
#define BCV  (BB*CC)      // 128
#define CAP  1024         // max support pixels per RF (analysis: <= ~930)
#define MAXJ 64           // max RFs covering one pixel (analysis: ~30)

// ---------------- static device scratch (no allocation allowed) -------------
__device__ int   g_cnt[KK];          // support size per k
__device__ int2  g_pk[KK*CAP];       // per-k list: {pixel, bits(rf*log2e)}
__device__ int   g_pxt[MAXJ*HWV];    // per-pixel lists, j-major, packed {rf|k}
__device__ int   g_pxc[HWV];         // per-pixel active-k count
__device__ float g_inv[BCV*KK];      // 1/(1+denom) per (bc,k)

__device__ __forceinline__ float ex2_fast(float y) {
    float r;
    asm("ex2.approx.f32 %0, %1;" : "=f"(r) : "f"(y));
    return r;
}

// ---------------- P: build per-k lists (blocks 0..63) and per-pixel ---------
// transposed lists (blocks 64..67). Deterministic orders everywhere.
__global__ __launch_bounds__(1024) void prep(const float* __restrict__ rfs) {
    const int tid = threadIdx.x;
    const float LOG2E = 1.4426950408889634f;

    if (blockIdx.x < 64) {
        // ---- per-k compact support list, raster order ----
        const int k    = blockIdx.x;
        const int lane = tid & 31;
        const int wid  = tid >> 5;
        __shared__ int wtot[32];
        __shared__ int woff[32];

        const float4 r = ((const float4*)(rfs + k*HWV))[tid];
        const int f0 = (r.x != 0.0f), f1 = (r.y != 0.0f), f2 = (r.z != 0.0f), f3 = (r.w != 0.0f);
        const int cnt = f0 + f1 + f2 + f3;

        int s = cnt;
        #pragma unroll
        for (int o = 1; o < 32; o <<= 1) {
            int t = __shfl_up_sync(0xffffffffu, s, o);
            if (lane >= o) s += t;
        }
        const int excl = s - cnt;
        if (lane == 31) wtot[wid] = s;
        __syncthreads();
        if (wid == 0) {
            int v = wtot[lane], ss = v;
            #pragma unroll
            for (int o = 1; o < 32; o <<= 1) {
                int t = __shfl_up_sync(0xffffffffu, ss, o);
                if (lane >= o) ss += t;
            }
            woff[lane] = ss - v;
            if (lane == 31) g_cnt[k] = (ss < CAP) ? ss : CAP;
        }
        __syncthreads();

        int base = woff[wid] + excl;
        const int p0 = tid * 4;
        int2* __restrict__ dst = g_pk + k*CAP;
        if (f0 && base < CAP) { dst[base] = make_int2(p0,     __float_as_int(r.x * LOG2E)); base++; }
        if (f1 && base < CAP) { dst[base] = make_int2(p0 + 1, __float_as_int(r.y * LOG2E)); base++; }
        if (f2 && base < CAP) { dst[base] = make_int2(p0 + 2, __float_as_int(r.z * LOG2E)); base++; }
        if (f3 && base < CAP) { dst[base] = make_int2(p0 + 3, __float_as_int(r.w * LOG2E)); base++; }
    } else {
        // ---- per-pixel transposed lists (j-major), k ascending ----
        const int p = (blockIdx.x - 64) * 1024 + tid;
        int c = 0;
        #pragma unroll 8
        for (int k = 0; k < KK; k++) {
            const float v = rfs[k*HWV + p];
            if (v != 0.0f) {
                // pack k into low 6 mantissa bits of rf*log2(e): <= 2^-17 rel err
                const int bits = (__float_as_int(v * LOG2E) & 0xFFFFFFC0) | k;
                g_pxt[c*HWV + p] = bits;
                c++;
            }
        }
        g_pxc[p] = c;
    }
}

// ---------------- K1: denominators.  block = (bc, chunk of 8 k) -------------
// exp(v - m)/(exp(-m) + sum exp(v - m)) == exp(v)/(1 + sum exp(v)).
// Per-k lists are raster-ordered -> the u gather is lane-coalesced LDG.
__global__ __launch_bounds__(128) void rf_denom(const float* __restrict__ u) {
    const int bc  = blockIdx.x >> 3;
    const int kc  = blockIdx.x & 7;
    const int tid = threadIdx.x;
    const int lane = tid & 31;
    const int wid  = tid >> 5;

    __shared__ float wred[2][4];
    const float* __restrict__ ub = u + bc*HWV;

    #pragma unroll
    for (int i = 0; i < 8; i++) {
        const int k = kc*8 + i;
        const int n = g_cnt[k];
        const int2* __restrict__ pr = g_pk + k*CAP + tid;

        float lsum = 0.0f;
        #pragma unroll
        for (int j = 0; j < 8; j++) {
            const int2 v = pr[j*128];            // in-bounds; zero-init beyond n
            if (tid + j*128 < n)
                lsum += ex2_fast(ub[v.x] * __int_as_float(v.y));
        }
        #pragma unroll
        for (int o = 16; o > 0; o >>= 1) lsum += __shfl_down_sync(0xffffffffu, lsum, o);
        if (lane == 0) wred[i & 1][wid] = lsum;
        __syncthreads();                         // publishes wred[i&1]; next write to it is i+2
        if (tid == 0) {
            const float s = wred[i & 1][0] + wred[i & 1][1] + wred[i & 1][2] + wred[i & 1][3];
            g_inv[bc*KK + k] = 1.0f / (1.0f + s);
        }
    }
}

// ---------------- K2: per-pixel numerators + 2x2 max pool -------------------
// block = (bc, quarter of the image = 16 rows). Thread interleaves 4 pixels
// (consecutive within warp -> coalesced LDG on u, counts, and j-major lists).
__global__ __launch_bounds__(256) void rf_hpool(const float* __restrict__ u,
                                                float* __restrict__ out) {
    const int bc  = blockIdx.x >> 2;
    const int seg = blockIdx.x & 3;
    const int tid = threadIdx.x;

    __shared__ float inv_s[KK];
    __shared__ float hs[1024];

    if (tid < KK) inv_s[tid] = g_inv[bc*KK + tid];
    __syncthreads();

    const int pbase = seg*1024 + tid;
    float uu[4], acc[4];
    int   n[4];
    #pragma unroll
    for (int q = 0; q < 4; q++) {
        const int p = pbase + q*256;
        n[q]   = g_pxc[p];
        uu[q]  = u[bc*HWV + p];
        acc[q] = 0.0f;
    }
    int nmax = max(max(n[0], n[1]), max(n[2], n[3]));

    for (int j = 0; j < nmax; j++) {
        #pragma unroll
        for (int q = 0; q < 4; q++) {
            if (j < n[q]) {
                const int bits = g_pxt[j*HWV + pbase + q*256];
                const int k    = bits & 63;
                const float rf = __int_as_float(bits & 0xFFFFFFC0);
                acc[q] += ex2_fast(uu[q] * rf) * inv_s[k];
            }
        }
    }

    #pragma unroll
    for (int q = 0; q < 4; q++) hs[tid + q*256] = acc[q];
    __syncthreads();

    // 2x2 max pool: thread -> one output
    const int ohl = tid >> 5;            // 0..7 within segment
    const int ow  = tid & 31;
    float best = 0.0f;                   // h >= 0 always (matches reference)
    #pragma unroll
    for (int dy = 0; dy < 2; dy++) {
        #pragma unroll
        for (int dx = 0; dx < 2; dx++)
            best = fmaxf(best, hs[(2*ohl + dy)*WW + 2*ow + dx]);
    }
    out[bc*(32*32) + (seg*8 + ohl)*32 + ow] = best;
}

// ---------------- launch -----------------------------------------------------
extern "C" void kernel_launch(void* const* d_in, const int* in_sizes, int n_in,
                              void* d_out, int out_size) {
    const float* u   = (const float*)d_in[0];   // (4,32,64,64)
    const float* rfs = (const float*)d_in[1];   // (64,64,64)
    float* out = (float*)d_out;                 // (4,32,32,32)

    prep     <<<68,   1024>>>(rfs);
    rf_denom <<<BCV*8, 128>>>(u);
    rf_hpool <<<BCV*4, 256>>>(u, out);
}

// round 7
// speedup vs baseline: 1.2898x; 1.2898x over previous
#include <cuda_runtime.h>

// Problem constants (fixed by the reference)
#define BB   4
#define CC   32
#define HH   64
#define WW   64
#define KK   64
#define HWV  (HH*WW)      // 4096
#define BCV  (BB*CC)      // 128
#define CAP  1024         // max support pixels per RF (analysis: <= ~930)
#define MAXJ 64           // max RFs covering one pixel (<= KK)

// ---------------- static device scratch (no allocation allowed) -------------
__device__ int g_cnt[KK];        // support size per k
__device__ int g_pk [KK*CAP];    // per-k list, 4B packed {rf20bits | pixel12}
__device__ int g_pxt[MAXJ*HWV];  // per-pixel lists, j-major, packed {rf26 | k6}
__device__ int g_pxc[HWV];       // per-pixel active-k count

__device__ __forceinline__ float ex2_fast(float y) {
    float r;
    asm("ex2.approx.f32 %0, %1;" : "=f"(r) : "f"(y));
    return r;
}

// ---------------- P: blocks 0..63 build per-k lists; 64..95 transposed ------
// lists. All orders fixed -> deterministic.
__global__ __launch_bounds__(1024) void prep(const float* __restrict__ rfs) {
    const int tid = threadIdx.x;
    const float LOG2E = 1.4426950408889634f;

    if (blockIdx.x < 64) {
        // ---- per-k compact support list, raster order, 4B packed ----
        const int k    = blockIdx.x;
        const int lane = tid & 31;
        const int wid  = tid >> 5;
        __shared__ int wtot[32];
        __shared__ int woff[32];

        const float4 r = ((const float4*)(rfs + k*HWV))[tid];
        const int f0 = (r.x != 0.0f), f1 = (r.y != 0.0f), f2 = (r.z != 0.0f), f3 = (r.w != 0.0f);
        const int cnt = f0 + f1 + f2 + f3;

        int s = cnt;
        #pragma unroll
        for (int o = 1; o < 32; o <<= 1) {
            int t = __shfl_up_sync(0xffffffffu, s, o);
            if (lane >= o) s += t;
        }
        const int excl = s - cnt;
        if (lane == 31) wtot[wid] = s;
        __syncthreads();
        if (wid == 0) {
            int v = wtot[lane], ss = v;
            #pragma unroll
            for (int o = 1; o < 32; o <<= 1) {
                int t = __shfl_up_sync(0xffffffffu, ss, o);
                if (lane >= o) ss += t;
            }
            woff[lane] = ss - v;
            if (lane == 31) g_cnt[k] = (ss < CAP) ? ss : CAP;
        }
        __syncthreads();

        // pack: round rf*log2e to 12 mantissa bits (unbiased), pixel in low 12
        int base = woff[wid] + excl;
        const int p0 = tid * 4;
        int* __restrict__ dst = g_pk + k*CAP;
        #define PACK_A(val, pix) ((( __float_as_int((val)*LOG2E) + 0x800) & 0xFFFFF000) | (pix))
        if (f0 && base < CAP) { dst[base] = PACK_A(r.x, p0);     base++; }
        if (f1 && base < CAP) { dst[base] = PACK_A(r.y, p0 + 1); base++; }
        if (f2 && base < CAP) { dst[base] = PACK_A(r.z, p0 + 2); base++; }
        if (f3 && base < CAP) { dst[base] = PACK_A(r.w, p0 + 3); base++; }
        #undef PACK_A
    } else {
        // ---- per-pixel transposed lists (j-major), k ascending ----
        // 32 blocks x 128 pixels; threads 128..1023 idle (no barriers here).
        if (tid >= 128) return;
        const int p = (blockIdx.x - 64) * 128 + tid;
        int c = 0;
        #pragma unroll 8
        for (int k = 0; k < KK; k++) {
            const float v = rfs[k*HWV + p];
            if (v != 0.0f) {
                // k in low 6 bits, rf*log2e rounded to 17 mantissa bits
                const int bits = ((__float_as_int(v * LOG2E) + 0x20) & 0xFFFFFFC0) | k;
                g_pxt[c*HWV + p] = bits;
                c++;
            }
        }
        g_pxc[p] = c;
    }
}

// ---------------- MAIN: one block per bc, two passes, ONE barrier -----------
// exp(v - m)/(exp(-m) + sum exp(v - m)) == exp(v)/(1 + sum exp(v)).
// Pass A: warp w reduces denominators of k = 2w, 2w+1 (pure shfl, no smem
//         RMW, no barriers) -> inv_s[k].
// Pass B: each thread owns 4 pixels; h[p] accumulated in REGISTERS by
//         re-evaluating exp and scaling with inv_s[k]. No scatter at all.
// Then 2x2 max pool from a 16KB smem exchange. All orders fixed.
__global__ __launch_bounds__(1024) void rf_main(const float* __restrict__ u,
                                                float* __restrict__ out) {
    __shared__ float us[HWV];      // 16 KB input tile
    __shared__ float hs[HWV];      // 16 KB h exchange for pooling
    __shared__ float inv_s[KK];

    const int bc   = blockIdx.x;
    const int tid  = threadIdx.x;
    const int lane = tid & 31;
    const int wid  = tid >> 5;

    // load u tile (coalesced float4)
    {
        const float4 v = ((const float4*)(u + bc*HWV))[tid];
        ((float4*)us)[tid] = v;
    }
    __syncthreads();

    // ---- pass A: denominators, warp-per-k ----
    #pragma unroll
    for (int i = 0; i < 2; i++) {
        const int k = wid*2 + i;
        const int n = g_cnt[k];
        const int* __restrict__ pr = g_pk + k*CAP;

        float sum = 0.0f;
        #pragma unroll 4
        for (int j = lane; j < n; j += 32) {
            const int bits = pr[j];                       // coalesced LDG.32
            const float rf = __int_as_float(bits & 0xFFFFF000);
            sum += ex2_fast(us[bits & 0xFFF] * rf);       // conflict-free LDS
        }
        #pragma unroll
        for (int o = 16; o > 0; o >>= 1) sum += __shfl_down_sync(0xffffffffu, sum, o);
        if (lane == 0) inv_s[k] = 1.0f / (1.0f + sum);
    }
    __syncthreads();                                      // the only barrier

    // ---- pass B: per-pixel numerators, register accumulation ----
    float uu[4], acc[4];
    int   n[4];
    #pragma unroll
    for (int q = 0; q < 4; q++) {
        const int p = tid + q*1024;
        n[q]   = g_pxc[p];
        uu[q]  = us[p];
        acc[q] = 0.0f;
    }
    const int nmax = max(max(n[0], n[1]), max(n[2], n[3]));

    for (int j = 0; j < nmax; j++) {
        #pragma unroll
        for (int q = 0; q < 4; q++) {
            if (j < n[q]) {
                const int bits = g_pxt[j*HWV + tid + q*1024];   // coalesced
                const float rf = __int_as_float(bits & 0xFFFFFFC0);
                acc[q] += ex2_fast(uu[q] * rf) * inv_s[bits & 63];
            }
        }
    }

    #pragma unroll
    for (int q = 0; q < 4; q++) hs[tid + q*1024] = acc[q];
    __syncthreads();

    // ---- 2x2 max pool: one output per thread ----
    const int oh = tid >> 5;
    const int ow = tid & 31;
    float best = 0.0f;                   // h >= 0 always (matches reference)
    #pragma unroll
    for (int dy = 0; dy < 2; dy++) {
        #pragma unroll
        for (int dx = 0; dx < 2; dx++)
            best = fmaxf(best, hs[(2*oh + dy)*WW + 2*ow + dx]);
    }
    out[bc*1024 + tid] = best;
}

// ---------------- launch -----------------------------------------------------
extern "C" void kernel_launch(void* const* d_in, const int* in_sizes, int n_in,
                              void* d_out, int out_size) {
    const float* u   = (const float*)d_in[0];   // (4,32,64,64)
    const float* rfs = (const float*)d_in[1];   // (64,64,64)
    float* out = (float*)d_out;                 // (4,32,32,32)

    prep   <<<96,  1024>>>(rfs);
    rf_main<<<BCV, 1024>>>(u, out);
}